// round 1
// baseline (speedup 1.0000x reference)
#include <cuda_runtime.h>
#include <cuda_bf16.h>
#include <math.h>

#define Nn 768
#define CS 384
#define CZ 128
#define CH 16
#define Hh 12
#define PQ 4
#define PV 8
#define NN2 (Nn*Nn)          // 589824
#define DCAT 2112            // H*(CH + PV*3 + PV + CZ) = 192+288+96+1536
#define INFV 100000.0f

// ---------------- scratch (device globals; no allocation) ----------------
__device__ float g_q[Nn*Hh*CH];        // (768,192)
__device__ float g_kv[Nn*2*Hh*CH];     // (768,384)
__device__ float g_qp[Nn*Hh*PQ*3];     // (768,144)
__device__ float g_kvp[Nn*Hh*(PQ+PV)*3]; // (768,432)
__device__ float g_qpts[Nn*Hh*PQ*3];     // rotated+translated
__device__ float g_kvpts[Nn*Hh*(PQ+PV)*3];
__device__ float g_b[Hh*NN2];          // bias b[h][i][j]
__device__ float g_a[Hh*NN2];          // softmaxed attention
__device__ float g_opt[Nn*Hh*PV*3];    // o_pt in global frame
__device__ float g_cat[Nn*DCAT];       // concat buffer

// ---------------- generic tiled SGEMM: C = A(MxK) * W(NoutxK)^T + bias ----------------
// All of M, Nout, K are multiples of 16 for every call site.
__global__ void sgemm_bias(const float* __restrict__ A, const float* __restrict__ W,
                           const float* __restrict__ bias, float* __restrict__ C,
                           int M, int Nout, int K) {
    __shared__ float As[16][16];
    __shared__ float Ws[16][17];
    int tx = threadIdx.x, ty = threadIdx.y;
    int m = blockIdx.y * 16 + ty;
    int nb = blockIdx.x * 16;
    float acc = 0.f;
    for (int k0 = 0; k0 < K; k0 += 16) {
        As[ty][tx] = A[m * K + k0 + tx];
        Ws[ty][tx] = W[(nb + ty) * K + k0 + tx];
        __syncthreads();
#pragma unroll
        for (int kk = 0; kk < 16; kk++) acc += As[ty][kk] * Ws[tx][kk];
        __syncthreads();
    }
    C[m * Nout + nb + tx] = acc + bias[nb + tx];
}

// ---------------- rotate+translate points ----------------
__global__ void point_kernel(const float* __restrict__ rot, const float* __restrict__ trans) {
    int i = blockIdx.x;
    int t = threadIdx.x;  // 0..191: first 48 = q pts (h*PQ+p), next 144 = kv pts (h*12+p)
    __shared__ float R[9], T[3];
    if (t < 9) R[t] = rot[i * 9 + t];
    if (t < 3) T[t] = trans[i * 3 + t];
    __syncthreads();
    if (t < 48) {
        const float* p = &g_qp[i * 144 + t * 3];
        float x = p[0], y = p[1], z = p[2];
        float* o = &g_qpts[i * 144 + t * 3];
        o[0] = R[0]*x + R[1]*y + R[2]*z + T[0];
        o[1] = R[3]*x + R[4]*y + R[5]*z + T[1];
        o[2] = R[6]*x + R[7]*y + R[8]*z + T[2];
    } else {
        int u = t - 48;
        const float* p = &g_kvp[i * 432 + u * 3];
        float x = p[0], y = p[1], z = p[2];
        float* o = &g_kvpts[i * 432 + u * 3];
        o[0] = R[0]*x + R[1]*y + R[2]*z + T[0];
        o[1] = R[3]*x + R[4]*y + R[5]*z + T[1];
        o[2] = R[6]*x + R[7]*y + R[8]*z + T[2];
    }
}

// ---------------- b[h][i*768+j] = z[i,j,:]·w_b[h,:] + b_b[h] ----------------
// 8 warps/block, one warp per (i,j) pair; staged shared write for coalescing.
__global__ void b_kernel(const float* __restrict__ z, const float* __restrict__ w_b,
                         const float* __restrict__ b_b) {
    __shared__ float wb[Hh * CZ];
    __shared__ float res[Hh][8];
    int tid = threadIdx.x;
    for (int u = tid; u < Hh * CZ; u += blockDim.x) wb[u] = w_b[u];
    __syncthreads();
    int warp = tid >> 5, lane = tid & 31;
    long pair = (long)blockIdx.x * 8 + warp;
    const float* zp = z + pair * CZ;
    float zv[4];
#pragma unroll
    for (int u = 0; u < 4; u++) zv[u] = zp[lane + 32 * u];
#pragma unroll
    for (int h = 0; h < Hh; h++) {
        float acc = 0.f;
#pragma unroll
        for (int u = 0; u < 4; u++) acc += zv[u] * wb[h * CZ + lane + 32 * u];
#pragma unroll
        for (int off = 16; off; off >>= 1) acc += __shfl_xor_sync(0xffffffffu, acc, off);
        if (lane == 0) res[h][warp] = acc + b_b[h];
    }
    __syncthreads();
    long base = (long)blockIdx.x * 8;
    if (tid < Hh * 8) {
        int h = tid >> 3, w = tid & 7;
        g_b[(long)h * NN2 + base + w] = res[h][w];
    }
}

// ---------------- logits + softmax, one block per (i,h) ----------------
__global__ void attn_kernel(const float* __restrict__ mask, const float* __restrict__ head_weights) {
    int i = blockIdx.x, h = blockIdx.y;
    __shared__ float qv[CH], qpt[PQ * 3], logits[Nn], red[256];
    int tid = threadIdx.x;
    if (tid < CH) qv[tid] = g_q[i * (Hh*CH) + h * CH + tid];
    if (tid < PQ * 3) qpt[tid] = g_qpts[i * 144 + h * 12 + tid];
    __syncthreads();
    float hwv = head_weights[h];
    float sp = (hwv > 20.f) ? hwv : log1pf(expf(hwv));
    float wc = -0.5f * sp * sqrtf(1.f / 54.f);
    const float scale1 = sqrtf(1.f / 48.f);
    const float s3 = sqrtf(1.f / 3.f);
    float mi = mask[i];
    const float* brow = &g_b[(long)h * NN2 + (long)i * Nn];
    for (int j = tid; j < Nn; j += 256) {
        const float* kk = &g_kv[j * 384 + h * 32];
        float qk = 0.f;
#pragma unroll
        for (int c = 0; c < CH; c++) qk += qv[c] * kk[c];
        const float* kp = &g_kvpts[j * 432 + h * 36];
        float d2 = 0.f;
#pragma unroll
        for (int p = 0; p < PQ; p++) {
            float dx = qpt[p*3+0] - kp[p*3+0];
            float dy = qpt[p*3+1] - kp[p*3+1];
            float dz = qpt[p*3+2] - kp[p*3+2];
            d2 += dx*dx + dy*dy + dz*dz;
        }
        logits[j] = qk * scale1 + s3 * brow[j] + wc * d2 + INFV * (mi * mask[j] - 1.f);
    }
    __syncthreads();
    float m = -1e30f;
    for (int j = tid; j < Nn; j += 256) m = fmaxf(m, logits[j]);
    red[tid] = m; __syncthreads();
    for (int s = 128; s; s >>= 1) { if (tid < s) red[tid] = fmaxf(red[tid], red[tid+s]); __syncthreads(); }
    float mx = red[0];
    __syncthreads();
    float sum = 0.f;
    for (int j = tid; j < Nn; j += 256) { float e = __expf(logits[j] - mx); logits[j] = e; sum += e; }
    red[tid] = sum; __syncthreads();
    for (int s = 128; s; s >>= 1) { if (tid < s) red[tid] += red[tid+s]; __syncthreads(); }
    float inv = 1.f / red[0];
    __syncthreads();
    float* arow = &g_a[(long)h * NN2 + (long)i * Nn];
    for (int j = tid; j < Nn; j += 256) arow[j] = logits[j] * inv;
}

// ---------------- o and o_pt: per (h, i-tile of 64) block ----------------
// 40 outputs per i: c<16 -> o[i,h,c]; c>=16 -> o_pt component (c-16) = p*3+x
__global__ void ov_kernel() {
    __shared__ float As[64][65];
    __shared__ float Vs[64][40];
    int h = blockIdx.y;
    int i0 = blockIdx.x * 64;
    int tid = threadIdx.x;            // 256 threads
    int ii = tid >> 2, cs = tid & 3;  // thread owns c = cs, cs+4, ..., cs+36
    float acc[10];
#pragma unroll
    for (int r = 0; r < 10; r++) acc[r] = 0.f;
    for (int j0 = 0; j0 < Nn; j0 += 64) {
        for (int u = tid; u < 64 * 64; u += 256) {
            int r = u >> 6, c = u & 63;
            As[r][c] = g_a[(long)h * NN2 + (long)(i0 + r) * Nn + j0 + c];
        }
        for (int u = tid; u < 64 * 40; u += 256) {
            int jj = u / 40, c = u % 40;
            float val;
            if (c < 16) val = g_kv[(j0 + jj) * 384 + h * 32 + 16 + c];
            else        val = g_kvpts[(j0 + jj) * 432 + h * 36 + 12 + (c - 16)];
            Vs[jj][c] = val;
        }
        __syncthreads();
#pragma unroll
        for (int jj = 0; jj < 64; jj++) {
            float av = As[ii][jj];
#pragma unroll
            for (int r = 0; r < 10; r++) acc[r] += av * Vs[jj][cs + 4 * r];
        }
        __syncthreads();
    }
    int i = i0 + ii;
#pragma unroll
    for (int r = 0; r < 10; r++) {
        int c = cs + 4 * r;
        if (c < 16) g_cat[i * DCAT + h * CH + c] = acc[r];
        else        g_opt[i * (Hh*PV*3) + h * (PV*3) + (c - 16)] = acc[r];
    }
}

// ---------------- o_pt -> local frame + norm ----------------
__global__ void epi_kernel(const float* __restrict__ rot, const float* __restrict__ trans) {
    int i = blockIdx.x;
    int t = threadIdx.x;  // 96 threads: h*PV+p
    __shared__ float R[9], T[3];
    if (t < 9) R[t] = rot[i * 9 + t];
    if (t < 3) T[t] = trans[i * 3 + t];
    __syncthreads();
    const float* op = &g_opt[i * (Hh*PV*3) + t * 3];
    float x = op[0] - T[0], y = op[1] - T[1], z = op[2] - T[2];
    float lx = R[0]*x + R[3]*y + R[6]*z;
    float ly = R[1]*x + R[4]*y + R[7]*z;
    float lz = R[2]*x + R[5]*y + R[8]*z;
    float nrm = sqrtf(lx*lx + ly*ly + lz*lz + 1e-8f);
    float* c1 = &g_cat[i * DCAT + Hh*CH + t * 3];
    c1[0] = lx; c1[1] = ly; c1[2] = lz;
    g_cat[i * DCAT + Hh*CH + Hh*PV*3 + t] = nrm;
}

// ---------------- o_pair[i,h,c] = sum_j a[h,i,j] z[i,j,c], one block per i ----------------
__global__ void opair_kernel(const float* __restrict__ z) {
    int i = blockIdx.x;
    __shared__ float zs[64][CZ];    // 32 KB
    __shared__ float as_[Hh][64];   // 3 KB
    int tid = threadIdx.x;          // 512 threads; each owns 3 (h,c) outputs
    int h0 = tid >> 7,          c0 = tid & 127;
    int h1 = (tid + 512) >> 7,  c1 = (tid + 512) & 127;
    int h2 = (tid + 1024) >> 7, c2 = (tid + 1024) & 127;
    float a0 = 0.f, a1 = 0.f, a2 = 0.f;
    for (int j0 = 0; j0 < Nn; j0 += 64) {
        for (int u = tid; u < 64 * CZ; u += 512)
            zs[u >> 7][u & 127] = z[((long)i * Nn + j0 + (u >> 7)) * CZ + (u & 127)];
        for (int u = tid; u < Hh * 64; u += 512)
            as_[u >> 6][u & 63] = g_a[(long)(u >> 6) * NN2 + (long)i * Nn + j0 + (u & 63)];
        __syncthreads();
#pragma unroll 8
        for (int jj = 0; jj < 64; jj++) {
            a0 += as_[h0][jj] * zs[jj][c0];
            a1 += as_[h1][jj] * zs[jj][c1];
            a2 += as_[h2][jj] * zs[jj][c2];
        }
        __syncthreads();
    }
    float* base = &g_cat[i * DCAT + Hh*CH + Hh*PV*3 + Hh*PV];
    base[tid] = a0; base[tid + 512] = a1; base[tid + 1024] = a2;
}

extern "C" void kernel_launch(void* const* d_in, const int* in_sizes, int n_in,
                              void* d_out, int out_size) {
    const float* s       = (const float*)d_in[0];
    const float* z       = (const float*)d_in[1];
    const float* rot     = (const float*)d_in[2];
    const float* trans   = (const float*)d_in[3];
    const float* mask    = (const float*)d_in[4];
    const float* w_q     = (const float*)d_in[5];
    const float* b_q     = (const float*)d_in[6];
    const float* w_kv    = (const float*)d_in[7];
    const float* b_kv    = (const float*)d_in[8];
    const float* w_qp    = (const float*)d_in[9];
    const float* b_qp    = (const float*)d_in[10];
    const float* w_kvp   = (const float*)d_in[11];
    const float* b_kvp   = (const float*)d_in[12];
    const float* w_b     = (const float*)d_in[13];
    const float* b_b     = (const float*)d_in[14];
    const float* head_w  = (const float*)d_in[15];
    const float* w_out   = (const float*)d_in[16];
    const float* b_out   = (const float*)d_in[17];
    float* out = (float*)d_out;

    float *gq, *gkv, *gqp, *gkvp, *gcat;
    cudaGetSymbolAddress((void**)&gq, g_q);
    cudaGetSymbolAddress((void**)&gkv, g_kv);
    cudaGetSymbolAddress((void**)&gqp, g_qp);
    cudaGetSymbolAddress((void**)&gkvp, g_kvp);
    cudaGetSymbolAddress((void**)&gcat, g_cat);

    dim3 t16(16, 16);
    // projections: C = s @ W^T + b
    sgemm_bias<<<dim3(Hh*CH/16, Nn/16), t16>>>(s, w_q,  b_q,  gq,  Nn, Hh*CH,   CS);
    sgemm_bias<<<dim3(2*Hh*CH/16, Nn/16), t16>>>(s, w_kv, b_kv, gkv, Nn, 2*Hh*CH, CS);
    sgemm_bias<<<dim3(Hh*PQ*3/16, Nn/16), t16>>>(s, w_qp, b_qp, gqp, Nn, Hh*PQ*3, CS);
    sgemm_bias<<<dim3(Hh*(PQ+PV)*3/16, Nn/16), t16>>>(s, w_kvp, b_kvp, gkvp, Nn, Hh*(PQ+PV)*3, CS);

    point_kernel<<<Nn, 192>>>(rot, trans);
    b_kernel<<<NN2 / 8, 256>>>(z, w_b, b_b);
    attn_kernel<<<dim3(Nn, Hh), 256>>>(mask, head_w);
    ov_kernel<<<dim3(Nn / 64, Hh), 256>>>();
    epi_kernel<<<Nn, 96>>>(rot, trans);
    opair_kernel<<<Nn, 512>>>(z);

    // final: out = cat @ w_out^T + b_out   (768 x 384, K = 2112)
    sgemm_bias<<<dim3(CS/16, Nn/16), t16>>>(gcat, w_out, b_out, out, Nn, CS, DCAT);
}

// round 2
// speedup vs baseline: 1.2695x; 1.2695x over previous
#include <cuda_runtime.h>
#include <cuda_bf16.h>
#include <math.h>

#define Nn 768
#define CS 384
#define CZ 128
#define CH 16
#define Hh 12
#define PQ 4
#define PV 8
#define NN2 (Nn*Nn)
#define DCAT 2112
#define INFV 100000.0f
#define S3 0.57735026918962576f   // sqrt(1/3)

// ---------------- scratch ----------------
__device__ float g_q[Nn*Hh*CH];
__device__ float g_kv[Nn*2*Hh*CH];
__device__ float g_qp[Nn*Hh*PQ*3];
__device__ float g_kvp[Nn*Hh*(PQ+PV)*3];
__device__ float g_qpts[Nn*Hh*PQ*3];
__device__ float g_kvpts[Nn*Hh*(PQ+PV)*3];
__device__ float g_T[Hh*68*Nn];        // [h][c][j]: c<16 k, 16..27 kpt, 28..67 v+vpts
__device__ float g_b[(long)Hh*NN2];    // pre-scaled by sqrt(1/3), bias added
__device__ float g_a[(long)Hh*NN2];
__device__ float g_opt[Nn*Hh*PV*3];
__device__ float g_cat[Nn*DCAT];

// ---------------- tiled GEMM: C = A(MxK) @ W(NoutxK)^T + bias ----------------
// TM=64 (M must be multiple of 64), TN=32 (Nout guarded), K multiple of 8.
__global__ void gemm_t(const float* __restrict__ A, const float* __restrict__ W,
                       const float* __restrict__ bias, float* __restrict__ C,
                       int M, int Nout, int K) {
    __shared__ float As[8][68];
    __shared__ float Ws[8][36];
    int tid = threadIdx.x;
    int m0 = blockIdx.y * 64, n0 = blockIdx.x * 32;
    int col = tid & 31, rg = tid >> 5;          // rg 0..7, rows rg*8..rg*8+7
    float acc[8];
#pragma unroll
    for (int t = 0; t < 8; t++) acc[t] = 0.f;
    int kk = tid & 7;
    int r  = tid >> 3;                          // 0..31
    for (int k0 = 0; k0 < K; k0 += 8) {
        As[kk][r]      = A[(m0 + r) * K + k0 + kk];
        As[kk][r + 32] = A[(m0 + r + 32) * K + k0 + kk];
        float wv = 0.f;
        if (n0 + r < Nout) wv = W[(n0 + r) * K + k0 + kk];
        Ws[kk][r] = wv;
        __syncthreads();
#pragma unroll
        for (int k2 = 0; k2 < 8; k2++) {
            float w2 = Ws[k2][col];
            float4 a0 = *(const float4*)&As[k2][rg * 8];
            float4 a1 = *(const float4*)&As[k2][rg * 8 + 4];
            acc[0] += a0.x * w2; acc[1] += a0.y * w2;
            acc[2] += a0.z * w2; acc[3] += a0.w * w2;
            acc[4] += a1.x * w2; acc[5] += a1.y * w2;
            acc[6] += a1.z * w2; acc[7] += a1.w * w2;
        }
        __syncthreads();
    }
    if (n0 + col < Nout) {
        float bv = bias[n0 + col];
#pragma unroll
        for (int t = 0; t < 8; t++)
            C[(m0 + rg * 8 + t) * Nout + n0 + col] = acc[t] + bv;
    }
}

// ---------------- rotate+translate points ----------------
__global__ void point_kernel(const float* __restrict__ rot, const float* __restrict__ trans) {
    int i = blockIdx.x;
    int t = threadIdx.x;
    __shared__ float R[9], T[3];
    if (t < 9) R[t] = rot[i * 9 + t];
    if (t < 3) T[t] = trans[i * 3 + t];
    __syncthreads();
    if (t < 48) {
        const float* p = &g_qp[i * 144 + t * 3];
        float x = p[0], y = p[1], z = p[2];
        float* o = &g_qpts[i * 144 + t * 3];
        o[0] = R[0]*x + R[1]*y + R[2]*z + T[0];
        o[1] = R[3]*x + R[4]*y + R[5]*z + T[1];
        o[2] = R[6]*x + R[7]*y + R[8]*z + T[2];
    } else {
        int u = t - 48;
        const float* p = &g_kvp[i * 432 + u * 3];
        float x = p[0], y = p[1], z = p[2];
        float* o = &g_kvpts[i * 432 + u * 3];
        o[0] = R[0]*x + R[1]*y + R[2]*z + T[0];
        o[1] = R[3]*x + R[4]*y + R[5]*z + T[1];
        o[2] = R[6]*x + R[7]*y + R[8]*z + T[2];
    }
}

// ---------------- transpose k/kpt/v into [h][c][j] for coalesced attn/ov ----------------
__global__ void transpose_kernel() {
    int c = blockIdx.x, h = blockIdx.y;
    int tid = threadIdx.x;
    const float* src; int stride;
    if (c < 16)      { src = g_kv    + h * 32 + c;            stride = 384; }
    else if (c < 28) { src = g_kvpts + h * 36 + (c - 16);     stride = 432; }
    else if (c < 44) { src = g_kv    + h * 32 + 16 + (c - 28); stride = 384; }
    else             { src = g_kvpts + h * 36 + 12 + (c - 44); stride = 432; }
    float* dst = g_T + (long)(h * 68 + c) * Nn;
    for (int j = tid; j < Nn; j += 256) dst[j] = src[(long)j * stride];
}

// ---------------- b = sqrt(1/3)*(z @ w_b^T + b_b), tiled over 64 pairs ----------------
__global__ void b_kernel(const float* __restrict__ z, const float* __restrict__ w_b,
                         const float* __restrict__ b_b) {
    __shared__ float zs[64][132];   // padded: conflict-free
    __shared__ float wb[12][128];
    int tid = threadIdx.x;
    long base = (long)blockIdx.x * 64;
    const float4* z4 = (const float4*)(z + base * CZ);
#pragma unroll
    for (int v = 0; v < 8; v++) {
        int idx = tid + v * 256;          // float4 index, 0..2047
        int row = idx >> 5, c4 = idx & 31;
        float4 val = z4[idx];
        *(float4*)&zs[row][4 * c4] = val;
    }
    for (int u = tid; u < 12 * 128; u += 256) wb[u >> 7][u & 127] = w_b[u];
    __syncthreads();
    int p = tid & 63, hb = tid >> 6;      // hb 0..3; heads hb, hb+4, hb+8
    float a0 = 0.f, a1 = 0.f, a2 = 0.f;
#pragma unroll
    for (int c4 = 0; c4 < 32; c4++) {
        float4 zv = *(const float4*)&zs[p][4 * c4];
        float4 w0 = *(const float4*)&wb[hb][4 * c4];
        float4 w1 = *(const float4*)&wb[hb + 4][4 * c4];
        float4 w2 = *(const float4*)&wb[hb + 8][4 * c4];
        a0 += zv.x*w0.x + zv.y*w0.y + zv.z*w0.z + zv.w*w0.w;
        a1 += zv.x*w1.x + zv.y*w1.y + zv.z*w1.z + zv.w*w1.w;
        a2 += zv.x*w2.x + zv.y*w2.y + zv.z*w2.z + zv.w*w2.w;
    }
    g_b[(long)hb * NN2 + base + p]       = S3 * (a0 + b_b[hb]);
    g_b[(long)(hb + 4) * NN2 + base + p] = S3 * (a1 + b_b[hb + 4]);
    g_b[(long)(hb + 8) * NN2 + base + p] = S3 * (a2 + b_b[hb + 8]);
}

// ---------------- logits + softmax, block per (i,h) ----------------
__global__ void attn_kernel(const float* __restrict__ mask, const float* __restrict__ head_weights) {
    int i = blockIdx.x, h = blockIdx.y;
    __shared__ float qv[CH], qpt[PQ * 3], logits[Nn], red[256];
    int tid = threadIdx.x;
    if (tid < CH) qv[tid] = g_q[i * (Hh*CH) + h * CH + tid];
    if (tid < PQ * 3) qpt[tid] = g_qpts[i * 144 + h * 12 + tid];
    __syncthreads();
    float hwv = head_weights[h];
    float sp = (hwv > 20.f) ? hwv : log1pf(expf(hwv));
    float wc = -0.5f * sp * sqrtf(1.f / 54.f);
    const float scale1 = sqrtf(1.f / 48.f);
    float mi = mask[i];
    const float* brow = &g_b[(long)h * NN2 + (long)i * Nn];
    const float* kT = &g_T[(long)(h * 68) * Nn];
    for (int j = tid; j < Nn; j += 256) {
        float qk = 0.f;
#pragma unroll
        for (int c = 0; c < CH; c++) qk += qv[c] * kT[c * Nn + j];
        float d2 = 0.f;
#pragma unroll
        for (int p = 0; p < PQ; p++) {
            float dx = qpt[p*3+0] - kT[(16 + p*3 + 0) * Nn + j];
            float dy = qpt[p*3+1] - kT[(16 + p*3 + 1) * Nn + j];
            float dz = qpt[p*3+2] - kT[(16 + p*3 + 2) * Nn + j];
            d2 += dx*dx + dy*dy + dz*dz;
        }
        logits[j] = qk * scale1 + brow[j] + wc * d2 + INFV * (mi * mask[j] - 1.f);
    }
    __syncthreads();
    float m = -1e30f;
    for (int j = tid; j < Nn; j += 256) m = fmaxf(m, logits[j]);
    red[tid] = m; __syncthreads();
    for (int s = 128; s; s >>= 1) { if (tid < s) red[tid] = fmaxf(red[tid], red[tid+s]); __syncthreads(); }
    float mx = red[0];
    __syncthreads();
    float sum = 0.f;
    for (int j = tid; j < Nn; j += 256) { float e = __expf(logits[j] - mx); logits[j] = e; sum += e; }
    red[tid] = sum; __syncthreads();
    for (int s = 128; s; s >>= 1) { if (tid < s) red[tid] += red[tid+s]; __syncthreads(); }
    float inv = 1.f / red[0];
    __syncthreads();
    float* arow = &g_a[(long)h * NN2 + (long)i * Nn];
    for (int j = tid; j < Nn; j += 256) arow[j] = logits[j] * inv;
}

// ---------------- o and o_pt: per (h, i-tile of 64) ----------------
__global__ void ov_kernel() {
    __shared__ float As[64][68];
    __shared__ float Vs[64][40];
    int h = blockIdx.y;
    int i0 = blockIdx.x * 64;
    int tid = threadIdx.x;
    int ii = tid >> 2, cs = tid & 3;
    float acc[10];
#pragma unroll
    for (int r = 0; r < 10; r++) acc[r] = 0.f;
    const float* vT = &g_T[(long)(h * 68 + 28) * Nn];
    for (int j0 = 0; j0 < Nn; j0 += 64) {
#pragma unroll
        for (int v = 0; v < 4; v++) {
            int idx = tid + v * 256;        // float4 idx over 64x16
            int row = idx >> 4, c4 = idx & 15;
            float4 val = *(const float4*)&g_a[(long)h * NN2 + (long)(i0 + row) * Nn + j0 + 4 * c4];
            *(float4*)&As[row][4 * c4] = val;
        }
        for (int u = tid; u < 64 * 40; u += 256) {
            int c = u >> 6, jj = u & 63;
            Vs[jj][c] = vT[(long)c * Nn + j0 + jj];
        }
        __syncthreads();
#pragma unroll
        for (int jj = 0; jj < 64; jj++) {
            float av = As[ii][jj];
#pragma unroll
            for (int r = 0; r < 10; r++) acc[r] += av * Vs[jj][cs + 4 * r];
        }
        __syncthreads();
    }
    int i = i0 + ii;
#pragma unroll
    for (int r = 0; r < 10; r++) {
        int c = cs + 4 * r;
        if (c < 16) g_cat[i * DCAT + h * CH + c] = acc[r];
        else        g_opt[i * (Hh*PV*3) + h * (PV*3) + (c - 16)] = acc[r];
    }
}

// ---------------- o_pt -> local frame + norm ----------------
__global__ void epi_kernel(const float* __restrict__ rot, const float* __restrict__ trans) {
    int i = blockIdx.x;
    int t = threadIdx.x;
    __shared__ float R[9], T[3];
    if (t < 9) R[t] = rot[i * 9 + t];
    if (t < 3) T[t] = trans[i * 3 + t];
    __syncthreads();
    const float* op = &g_opt[i * (Hh*PV*3) + t * 3];
    float x = op[0] - T[0], y = op[1] - T[1], z = op[2] - T[2];
    float lx = R[0]*x + R[3]*y + R[6]*z;
    float ly = R[1]*x + R[4]*y + R[7]*z;
    float lz = R[2]*x + R[5]*y + R[8]*z;
    float nrm = sqrtf(lx*lx + ly*ly + lz*lz + 1e-8f);
    float* c1 = &g_cat[i * DCAT + Hh*CH + t * 3];
    c1[0] = lx; c1[1] = ly; c1[2] = lz;
    g_cat[i * DCAT + Hh*CH + Hh*PV*3 + t] = nrm;
}

// ---------------- o_pair: block per i, warp per head, float4 per lane ----------------
__global__ void opair_kernel(const float* __restrict__ z) {
    __shared__ float zs[64][128];
    __shared__ float as_[Hh][64];
    int i = blockIdx.x;
    int tid = threadIdx.x;                 // 384 threads = 12 warps
    int h = tid >> 5, l = tid & 31;        // warp h, lane owns c = 4l..4l+3
    float4 acc = make_float4(0.f, 0.f, 0.f, 0.f);
    for (int j0 = 0; j0 < Nn; j0 += 64) {
        const float4* z4 = (const float4*)(z + ((long)i * Nn + j0) * CZ);
        for (int u = tid; u < 64 * 32; u += 384) {   // float4 units
            int row = u >> 5, c4 = u & 31;
            *(float4*)&zs[row][4 * c4] = z4[u];
        }
        for (int u = tid; u < Hh * 64; u += 384) {
            int hh = u >> 6, jj = u & 63;
            as_[hh][jj] = g_a[(long)hh * NN2 + (long)i * Nn + j0 + jj];
        }
        __syncthreads();
#pragma unroll 8
        for (int jj = 0; jj < 64; jj++) {
            float av = as_[h][jj];
            float4 zv = *(const float4*)&zs[jj][4 * l];
            acc.x += av * zv.x; acc.y += av * zv.y;
            acc.z += av * zv.z; acc.w += av * zv.w;
        }
        __syncthreads();
    }
    *(float4*)&g_cat[i * DCAT + 576 + h * CZ + 4 * l] = acc;
}

extern "C" void kernel_launch(void* const* d_in, const int* in_sizes, int n_in,
                              void* d_out, int out_size) {
    const float* s       = (const float*)d_in[0];
    const float* z       = (const float*)d_in[1];
    const float* rot     = (const float*)d_in[2];
    const float* trans   = (const float*)d_in[3];
    const float* mask    = (const float*)d_in[4];
    const float* w_q     = (const float*)d_in[5];
    const float* b_q     = (const float*)d_in[6];
    const float* w_kv    = (const float*)d_in[7];
    const float* b_kv    = (const float*)d_in[8];
    const float* w_qp    = (const float*)d_in[9];
    const float* b_qp    = (const float*)d_in[10];
    const float* w_kvp   = (const float*)d_in[11];
    const float* b_kvp   = (const float*)d_in[12];
    const float* w_b     = (const float*)d_in[13];
    const float* b_b     = (const float*)d_in[14];
    const float* head_w  = (const float*)d_in[15];
    const float* w_out   = (const float*)d_in[16];
    const float* b_out   = (const float*)d_in[17];
    float* out = (float*)d_out;

    float *gq, *gkv, *gqp, *gkvp, *gcat;
    cudaGetSymbolAddress((void**)&gq, g_q);
    cudaGetSymbolAddress((void**)&gkv, g_kv);
    cudaGetSymbolAddress((void**)&gqp, g_qp);
    cudaGetSymbolAddress((void**)&gkvp, g_kvp);
    cudaGetSymbolAddress((void**)&gcat, g_cat);

    gemm_t<<<dim3(6, 12), 256>>>(s, w_q,  b_q,  gq,  Nn, Hh*CH,        CS);
    gemm_t<<<dim3(12, 12), 256>>>(s, w_kv, b_kv, gkv, Nn, 2*Hh*CH,     CS);
    gemm_t<<<dim3(5, 12), 256>>>(s, w_qp, b_qp, gqp, Nn, Hh*PQ*3,      CS);
    gemm_t<<<dim3(14, 12), 256>>>(s, w_kvp, b_kvp, gkvp, Nn, Hh*(PQ+PV)*3, CS);

    point_kernel<<<Nn, 192>>>(rot, trans);
    transpose_kernel<<<dim3(68, 12), 256>>>();
    b_kernel<<<NN2 / 64, 256>>>(z, w_b, b_b);
    attn_kernel<<<dim3(Nn, Hh), 256>>>(mask, head_w);
    ov_kernel<<<dim3(Nn / 64, Hh), 256>>>();
    epi_kernel<<<Nn, 96>>>(rot, trans);
    opair_kernel<<<Nn, 384>>>(z);

    gemm_t<<<dim3(12, 12), 256>>>(gcat, w_out, b_out, out, Nn, CS, DCAT);
}

// round 4
// speedup vs baseline: 2.1236x; 1.6727x over previous
#include <cuda_runtime.h>
#include <math.h>

#define Nn 768
#define CS 384
#define CZ 128
#define Hh 12
#define NN2 (Nn*Nn)
#define DCAT 2112
#define NPROJ 1152
#define INFV 100000.0f
#define S3 0.57735026918962576f

// ---------------- scratch ----------------
__device__ float g_proj[Nn*NPROJ];     // cols: [0,192) q | [192,576) kv | [576,720) qp | [720,1152) kvp
__device__ float g_qpts[Nn*144];
__device__ float g_kvpts[Nn*432];
__device__ float g_T[Hh*68*Nn];        // [h][c][j]: 0..15 k, 16..27 kpt, 28..43 v, 44..67 vpt
__device__ float g_a[(long)Hh*NN2];
__device__ float g_opt[Nn*288];
__device__ float g_cat[Nn*DCAT];

typedef unsigned long long ull;
__device__ __forceinline__ void fma2(ull& d, ull a, ull b) {
    asm("fma.rn.f32x2 %0, %1, %2, %3;" : "=l"(d) : "l"(a), "l"(b), "l"(d));
}
__device__ __forceinline__ ull add2(ull a, ull b) {
    ull d; asm("add.rn.f32x2 %0, %1, %2;" : "=l"(d) : "l"(a), "l"(b)); return d;
}
__device__ __forceinline__ ull packdup(float x) {
    ull d; asm("mov.b64 %0, {%1, %1};" : "=l"(d) : "f"(x)); return d;
}
__device__ __forceinline__ float2 unpk(ull d) {
    float2 r; asm("mov.b64 {%0, %1}, %2;" : "=f"(r.x), "=f"(r.y) : "l"(d)); return r;
}

// ---------------- fused projections: g_proj = s @ [w_q|w_kv|w_qp|w_kvp]^T + biases ----------------
__global__ void proj_gemm(const float* __restrict__ s,
    const float* __restrict__ w_q, const float* __restrict__ b_q,
    const float* __restrict__ w_kv, const float* __restrict__ b_kv,
    const float* __restrict__ w_qp, const float* __restrict__ b_qp,
    const float* __restrict__ w_kvp, const float* __restrict__ b_kvp) {
    __shared__ float As[16][68];
    __shared__ float Ws[16][33];
    int tid = threadIdx.x;
    int m0 = blockIdx.y * 64, n0 = blockIdx.x * 32;
    int col = tid & 31, rg = tid >> 5;
    int ar = tid >> 2, akg = tid & 3;
    ull acc0 = 0, acc1 = 0, acc2 = 0, acc3 = 0;
    const float* wrow = nullptr;
    int wc = tid >> 2, wkg = tid & 3;
    if (tid < 128) {
        int gc = n0 + wc;
        const float* W; int lc;
        if (gc < 192)      { W = w_q;   lc = gc; }
        else if (gc < 576) { W = w_kv;  lc = gc - 192; }
        else if (gc < 720) { W = w_qp;  lc = gc - 576; }
        else               { W = w_kvp; lc = gc - 720; }
        wrow = W + lc * CS;
    }
    for (int k0 = 0; k0 < CS; k0 += 16) {
        float4 av = *(const float4*)&s[(m0 + ar) * CS + k0 + 4 * akg];
        As[4*akg+0][ar] = av.x; As[4*akg+1][ar] = av.y;
        As[4*akg+2][ar] = av.z; As[4*akg+3][ar] = av.w;
        if (tid < 128) {
            float4 wv = *(const float4*)&wrow[k0 + 4 * wkg];
            Ws[4*wkg+0][wc] = wv.x; Ws[4*wkg+1][wc] = wv.y;
            Ws[4*wkg+2][wc] = wv.z; Ws[4*wkg+3][wc] = wv.w;
        }
        __syncthreads();
#pragma unroll
        for (int k2 = 0; k2 < 16; k2++) {
            ull w2 = packdup(Ws[k2][col]);
            ulonglong2 a0 = *(const ulonglong2*)&As[k2][rg * 8];
            ulonglong2 a1 = *(const ulonglong2*)&As[k2][rg * 8 + 4];
            fma2(acc0, a0.x, w2); fma2(acc1, a0.y, w2);
            fma2(acc2, a1.x, w2); fma2(acc3, a1.y, w2);
        }
        __syncthreads();
    }
    int gc = n0 + col;
    float bv;
    if (gc < 192)      bv = b_q[gc];
    else if (gc < 576) bv = b_kv[gc - 192];
    else if (gc < 720) bv = b_qp[gc - 576];
    else               bv = b_kvp[gc - 720];
    int mb = m0 + rg * 8;
    float2 r;
    r = unpk(acc0); g_proj[(mb+0)*NPROJ+gc] = r.x+bv; g_proj[(mb+1)*NPROJ+gc] = r.y+bv;
    r = unpk(acc1); g_proj[(mb+2)*NPROJ+gc] = r.x+bv; g_proj[(mb+3)*NPROJ+gc] = r.y+bv;
    r = unpk(acc2); g_proj[(mb+4)*NPROJ+gc] = r.x+bv; g_proj[(mb+5)*NPROJ+gc] = r.y+bv;
    r = unpk(acc3); g_proj[(mb+6)*NPROJ+gc] = r.x+bv; g_proj[(mb+7)*NPROJ+gc] = r.y+bv;
}

// ---------------- output GEMM: out = g_cat @ w_out^T + b_out ----------------
__global__ void gemm_out(const float* __restrict__ W, const float* __restrict__ bias,
                         float* __restrict__ C) {
    __shared__ float As[16][68];
    __shared__ float Ws[16][33];
    int tid = threadIdx.x;
    int m0 = blockIdx.y * 64, n0 = blockIdx.x * 32;
    int col = tid & 31, rg = tid >> 5;
    int ar = tid >> 2, akg = tid & 3;
    ull acc0 = 0, acc1 = 0, acc2 = 0, acc3 = 0;
    int wc = tid >> 2, wkg = tid & 3;
    const float* wrow = W + (n0 + wc) * DCAT;
    for (int k0 = 0; k0 < DCAT; k0 += 16) {
        float4 av = *(const float4*)&g_cat[(m0 + ar) * DCAT + k0 + 4 * akg];
        As[4*akg+0][ar] = av.x; As[4*akg+1][ar] = av.y;
        As[4*akg+2][ar] = av.z; As[4*akg+3][ar] = av.w;
        if (tid < 128) {
            float4 wv = *(const float4*)&wrow[k0 + 4 * wkg];
            Ws[4*wkg+0][wc] = wv.x; Ws[4*wkg+1][wc] = wv.y;
            Ws[4*wkg+2][wc] = wv.z; Ws[4*wkg+3][wc] = wv.w;
        }
        __syncthreads();
#pragma unroll
        for (int k2 = 0; k2 < 16; k2++) {
            ull w2 = packdup(Ws[k2][col]);
            ulonglong2 a0 = *(const ulonglong2*)&As[k2][rg * 8];
            ulonglong2 a1 = *(const ulonglong2*)&As[k2][rg * 8 + 4];
            fma2(acc0, a0.x, w2); fma2(acc1, a0.y, w2);
            fma2(acc2, a1.x, w2); fma2(acc3, a1.y, w2);
        }
        __syncthreads();
    }
    float bv = bias[n0 + col];
    int mb = m0 + rg * 8, gc = n0 + col;
    float2 r;
    r = unpk(acc0); C[(mb+0)*384+gc] = r.x+bv; C[(mb+1)*384+gc] = r.y+bv;
    r = unpk(acc1); C[(mb+2)*384+gc] = r.x+bv; C[(mb+3)*384+gc] = r.y+bv;
    r = unpk(acc2); C[(mb+4)*384+gc] = r.x+bv; C[(mb+5)*384+gc] = r.y+bv;
    r = unpk(acc3); C[(mb+6)*384+gc] = r.x+bv; C[(mb+7)*384+gc] = r.y+bv;
}

// ---------------- rotate+translate points ----------------
__global__ void point_kernel(const float* __restrict__ rot, const float* __restrict__ trans) {
    int i = blockIdx.x;
    int t = threadIdx.x;
    __shared__ float R[9], T[3];
    if (t < 9) R[t] = rot[i * 9 + t];
    if (t < 3) T[t] = trans[i * 3 + t];
    __syncthreads();
    if (t < 48) {
        const float* p = &g_proj[i * NPROJ + 576 + t * 3];
        float x = p[0], y = p[1], z = p[2];
        float* o = &g_qpts[i * 144 + t * 3];
        o[0] = R[0]*x + R[1]*y + R[2]*z + T[0];
        o[1] = R[3]*x + R[4]*y + R[5]*z + T[1];
        o[2] = R[6]*x + R[7]*y + R[8]*z + T[2];
    } else {
        int u = t - 48;
        const float* p = &g_proj[i * NPROJ + 720 + u * 3];
        float x = p[0], y = p[1], z = p[2];
        float* o = &g_kvpts[i * 432 + u * 3];
        o[0] = R[0]*x + R[1]*y + R[2]*z + T[0];
        o[1] = R[3]*x + R[4]*y + R[5]*z + T[1];
        o[2] = R[6]*x + R[7]*y + R[8]*z + T[2];
    }
}

// ---------------- transpose into [h][c][j] ----------------
__global__ void transpose_kernel() {
    int c = blockIdx.x, h = blockIdx.y;
    int tid = threadIdx.x;
    const float* src; int stride;
    if (c < 16)      { src = g_proj  + 192 + h * 32 + c;             stride = NPROJ; }
    else if (c < 28) { src = g_kvpts + h * 36 + (c - 16);            stride = 432; }
    else if (c < 44) { src = g_proj  + 192 + h * 32 + 16 + (c - 28); stride = NPROJ; }
    else             { src = g_kvpts + h * 36 + 12 + (c - 44);       stride = 432; }
    float* dst = g_T + (long)(h * 68 + c) * Nn;
    for (int j = tid; j < Nn; j += 256) dst[j] = src[(long)j * stride];
}

// ---------------- fused bias + logits + softmax: one block per i, 384 threads ----------------
__global__ void attn_fused(const float* __restrict__ z, const float* __restrict__ w_b,
                           const float* __restrict__ b_b, const float* __restrict__ mask,
                           const float* __restrict__ head_w) {
    extern __shared__ float sm[];
    float* zs  = sm;            // [64][132]   8448
    float* wb  = sm + 8448;     // [12][128]   1536
    float* lg  = sm + 9984;     // [12][768]   9216
    float* qv  = sm + 19200;    // [12][16]     192
    float* qpt = sm + 19392;    // [12][12]     144
    float* wcs = sm + 19536;    // [12]
    int i = blockIdx.x, tid = threadIdx.x;
    for (int u = tid; u < 1536; u += 384) wb[u] = w_b[u];
    if (tid < 192) qv[tid] = g_proj[i * NPROJ + tid];
    else if (tid < 336) qpt[tid - 192] = g_qpts[i * 144 + (tid - 192)];
    else if (tid < 348) {
        int h = tid - 336;
        float hw = head_w[h];
        float sp = (hw > 20.f) ? hw : log1pf(expf(hw));
        wcs[h] = -0.5f * sp * 0.13608276348795434f;  // sqrt(1/54)
    }
    __syncthreads();

    int p = tid & 63, hb = tid >> 6;     // hb 0..5 -> heads hb, hb+6
    for (int j0 = 0; j0 < Nn; j0 += 64) {
        const float4* z4 = (const float4*)(z + ((long)i * Nn + j0) * CZ);
        for (int u = tid; u < 2048; u += 384) {
            float4 v = z4[u];
            *(float4*)&zs[(u >> 5) * 132 + (u & 31) * 4] = v;
        }
        __syncthreads();
        ull aL0 = 0, aH0 = 0, aL1 = 0, aH1 = 0;
        const float* wr0 = wb + hb * 128;
        const float* wr1 = wb + (hb + 6) * 128;
        const float* zr = zs + p * 132;
#pragma unroll
        for (int c4 = 0; c4 < 32; c4++) {
            ulonglong2 zv = *(const ulonglong2*)&zr[4 * c4];
            ulonglong2 w0 = *(const ulonglong2*)&wr0[4 * c4];
            ulonglong2 w1 = *(const ulonglong2*)&wr1[4 * c4];
            fma2(aL0, zv.x, w0.x); fma2(aH0, zv.y, w0.y);
            fma2(aL1, zv.x, w1.x); fma2(aH1, zv.y, w1.y);
        }
        float2 u0 = unpk(aL0), v0 = unpk(aH0);
        float2 u1 = unpk(aL1), v1 = unpk(aH1);
        lg[hb * Nn + j0 + p]       = S3 * ((u0.x + u0.y + v0.x + v0.y) + b_b[hb]);
        lg[(hb + 6) * Nn + j0 + p] = S3 * ((u1.x + u1.y + v1.x + v1.y) + b_b[hb + 6]);
        __syncthreads();
    }

    float mi = mask[i];
    const float scale1 = 0.14433756729740643f;  // sqrt(1/48)
    for (int u = tid; u < Hh * Nn; u += 384) {
        int h = u / Nn, j = u - h * Nn;
        const float* kT = g_T + (long)h * 68 * Nn;
        const float* qh = qv + h * 16;
        float qk = 0.f;
#pragma unroll
        for (int c = 0; c < 16; c++) qk += qh[c] * kT[c * Nn + j];
        const float* qp = qpt + h * 12;
        float d2 = 0.f;
#pragma unroll
        for (int pp = 0; pp < 4; pp++) {
            float dx = qp[pp*3+0] - kT[(16 + pp*3 + 0) * Nn + j];
            float dy = qp[pp*3+1] - kT[(16 + pp*3 + 1) * Nn + j];
            float dz = qp[pp*3+2] - kT[(16 + pp*3 + 2) * Nn + j];
            d2 += dx*dx + dy*dy + dz*dz;
        }
        lg[u] += qk * scale1 + wcs[h] * d2 + INFV * (mi * mask[j] - 1.f);
    }
    __syncthreads();

    // softmax: warp per head
    int w = tid >> 5, lane = tid & 31;
    float* row = lg + w * Nn;
    float m = -1e30f;
    for (int j = lane; j < Nn; j += 32) m = fmaxf(m, row[j]);
#pragma unroll
    for (int o = 16; o; o >>= 1) m = fmaxf(m, __shfl_xor_sync(~0u, m, o));
    float ssum = 0.f;
    for (int j = lane; j < Nn; j += 32) { float e = __expf(row[j] - m); row[j] = e; ssum += e; }
#pragma unroll
    for (int o = 16; o; o >>= 1) ssum += __shfl_xor_sync(~0u, ssum, o);
    float inv = 1.f / ssum;
    float* arow = g_a + (long)w * NN2 + (long)i * Nn;
    for (int j = lane; j < Nn; j += 32) arow[j] = row[j] * inv;
}

// ---------------- o and o_pt: per (h, i-tile 64) ----------------
__global__ void ov_kernel() {
    __shared__ float As[64][68];
    __shared__ float Vs[64][40];
    int h = blockIdx.y;
    int i0 = blockIdx.x * 64;
    int tid = threadIdx.x;
    int ii = tid >> 2, cs = tid & 3;
    float acc[10];
#pragma unroll
    for (int r = 0; r < 10; r++) acc[r] = 0.f;
    const float* vT = &g_T[(long)(h * 68 + 28) * Nn];
    for (int j0 = 0; j0 < Nn; j0 += 64) {
#pragma unroll
        for (int v = 0; v < 4; v++) {
            int idx = tid + v * 256;
            int row = idx >> 4, c4 = idx & 15;
            float4 val = *(const float4*)&g_a[(long)h * NN2 + (long)(i0 + row) * Nn + j0 + 4 * c4];
            *(float4*)&As[row][4 * c4] = val;
        }
        for (int u = tid; u < 64 * 40; u += 256) {
            int c = u >> 6, jj = u & 63;
            Vs[jj][c] = vT[(long)c * Nn + j0 + jj];
        }
        __syncthreads();
#pragma unroll
        for (int jj = 0; jj < 64; jj++) {
            float av = As[ii][jj];
#pragma unroll
            for (int r = 0; r < 10; r++) acc[r] += av * Vs[jj][cs + 4 * r];
        }
        __syncthreads();
    }
    int i = i0 + ii;
#pragma unroll
    for (int r = 0; r < 10; r++) {
        int c = cs + 4 * r;
        if (c < 16) g_cat[i * DCAT + h * 16 + c] = acc[r];
        else        g_opt[i * 288 + h * 24 + (c - 16)] = acc[r];
    }
}

// ---------------- o_pt -> local frame + norm ----------------
__global__ void epi_kernel(const float* __restrict__ rot, const float* __restrict__ trans) {
    int i = blockIdx.x;
    int t = threadIdx.x;
    __shared__ float R[9], T[3];
    if (t < 9) R[t] = rot[i * 9 + t];
    if (t < 3) T[t] = trans[i * 3 + t];
    __syncthreads();
    const float* op = &g_opt[i * 288 + t * 3];
    float x = op[0] - T[0], y = op[1] - T[1], z = op[2] - T[2];
    float lx = R[0]*x + R[3]*y + R[6]*z;
    float ly = R[1]*x + R[4]*y + R[7]*z;
    float lz = R[2]*x + R[5]*y + R[8]*z;
    float nrm = sqrtf(lx*lx + ly*ly + lz*lz + 1e-8f);
    float* c1 = &g_cat[i * DCAT + 192 + t * 3];
    c1[0] = lx; c1[1] = ly; c1[2] = lz;
    g_cat[i * DCAT + 480 + t] = nrm;
}

// ---------------- o_pair: block per i, 256 threads ----------------
__global__ void opair_fused(const float* __restrict__ z) {
    extern __shared__ float sm[];
    float* zs  = sm;           // [64][132]  8448
    float* as_ = sm + 8448;    // [12][64]    768
    float* red = sm + 9216;    // [4][12][128] 6144
    int i = blockIdx.x, tid = threadIdx.x;
    int c4 = tid & 31, jg = tid >> 5;
    ull accL[12], accH[12];
#pragma unroll
    for (int h = 0; h < 12; h++) { accL[h] = 0; accH[h] = 0; }
    for (int j0 = 0; j0 < Nn; j0 += 64) {
        const float4* z4 = (const float4*)(z + ((long)i * Nn + j0) * CZ);
        for (int u = tid; u < 2048; u += 256) {
            float4 v = z4[u];
            *(float4*)&zs[(u >> 5) * 132 + (u & 31) * 4] = v;
        }
        for (int u = tid; u < 768; u += 256)
            as_[u] = g_a[(long)(u >> 6) * NN2 + (long)i * Nn + j0 + (u & 63)];
        __syncthreads();
#pragma unroll
        for (int k = 0; k < 8; k++) {
            int jj = jg + 8 * k;
            ulonglong2 zv = *(const ulonglong2*)&zs[jj * 132 + 4 * c4];
#pragma unroll
            for (int h = 0; h < 12; h++) {
                ull av2 = packdup(as_[h * 64 + jj]);
                fma2(accL[h], av2, zv.x);
                fma2(accH[h], av2, zv.y);
            }
        }
        __syncthreads();
    }
    // tree-reduce 8 j-groups -> 1
    if (jg >= 4) {
#pragma unroll
        for (int h = 0; h < 12; h++)
            *(ulonglong2*)&red[(jg - 4) * 1536 + h * 128 + 4 * c4] = make_ulonglong2(accL[h], accH[h]);
    }
    __syncthreads();
    if (jg < 4) {
#pragma unroll
        for (int h = 0; h < 12; h++) {
            ulonglong2 r = *(const ulonglong2*)&red[jg * 1536 + h * 128 + 4 * c4];
            accL[h] = add2(accL[h], r.x); accH[h] = add2(accH[h], r.y);
        }
    }
    __syncthreads();
    if (jg == 2 || jg == 3) {
#pragma unroll
        for (int h = 0; h < 12; h++)
            *(ulonglong2*)&red[(jg - 2) * 1536 + h * 128 + 4 * c4] = make_ulonglong2(accL[h], accH[h]);
    }
    __syncthreads();
    if (jg < 2) {
#pragma unroll
        for (int h = 0; h < 12; h++) {
            ulonglong2 r = *(const ulonglong2*)&red[jg * 1536 + h * 128 + 4 * c4];
            accL[h] = add2(accL[h], r.x); accH[h] = add2(accH[h], r.y);
        }
    }
    __syncthreads();
    if (jg == 1) {
#pragma unroll
        for (int h = 0; h < 12; h++)
            *(ulonglong2*)&red[h * 128 + 4 * c4] = make_ulonglong2(accL[h], accH[h]);
    }
    __syncthreads();
    if (jg == 0) {
#pragma unroll
        for (int h = 0; h < 12; h++) {
            ulonglong2 r = *(const ulonglong2*)&red[h * 128 + 4 * c4];
            accL[h] = add2(accL[h], r.x); accH[h] = add2(accH[h], r.y);
            *(ulonglong2*)&g_cat[i * DCAT + 576 + h * 128 + 4 * c4] = make_ulonglong2(accL[h], accH[h]);
        }
    }
}

extern "C" void kernel_launch(void* const* d_in, const int* in_sizes, int n_in,
                              void* d_out, int out_size) {
    const float* s       = (const float*)d_in[0];
    const float* z       = (const float*)d_in[1];
    const float* rot     = (const float*)d_in[2];
    const float* trans   = (const float*)d_in[3];
    const float* mask    = (const float*)d_in[4];
    const float* w_q     = (const float*)d_in[5];
    const float* b_q     = (const float*)d_in[6];
    const float* w_kv    = (const float*)d_in[7];
    const float* b_kv    = (const float*)d_in[8];
    const float* w_qp    = (const float*)d_in[9];
    const float* b_qp    = (const float*)d_in[10];
    const float* w_kvp   = (const float*)d_in[11];
    const float* b_kvp   = (const float*)d_in[12];
    const float* w_b     = (const float*)d_in[13];
    const float* b_b     = (const float*)d_in[14];
    const float* head_w  = (const float*)d_in[15];
    const float* w_out   = (const float*)d_in[16];
    const float* b_out   = (const float*)d_in[17];
    float* out = (float*)d_out;

    // deterministic, host-side, capture-safe (not a stream op); no static guards
    cudaFuncSetAttribute(attn_fused, cudaFuncAttributeMaxDynamicSharedMemorySize, 78208);
    cudaFuncSetAttribute(opair_fused, cudaFuncAttributeMaxDynamicSharedMemorySize, 61440);

    proj_gemm<<<dim3(36, 12), 256>>>(s, w_q, b_q, w_kv, b_kv, w_qp, b_qp, w_kvp, b_kvp);
    point_kernel<<<Nn, 192>>>(rot, trans);
    transpose_kernel<<<dim3(68, 12), 256>>>();
    attn_fused<<<Nn, 384, 78208>>>(z, w_b, b_b, mask, head_w);
    ov_kernel<<<dim3(Nn / 64, Hh), 256>>>();
    epi_kernel<<<Nn, 96>>>(rot, trans);
    opair_fused<<<Nn, 256, 61440>>>(z);
    gemm_out<<<dim3(12, 12), 256>>>(w_out, b_out, out);
}

// round 17
// speedup vs baseline: 2.3722x; 1.1170x over previous
#include <cuda_runtime.h>
#include <math.h>

#define Nn 768
#define CS 384
#define CZ 128
#define Hh 12
#define NN2 (Nn*Nn)
#define DCAT 2112
#define NPROJ 1152
#define INFV 100000.0f
#define S3 0.57735026918962576f

// ---------------- scratch ----------------
__device__ float g_proj[Nn*NPROJ];
__device__ float g_qpts[Nn*144];
__device__ float g_kvpts[Nn*432];
__device__ float g_T[Hh*68*Nn];          // [h][c][j]: 0..15 k, 16..27 kpt, 28..43 v, 44..67 vpt
__device__ float g_bt[(long)Hh*NN2];     // bias, layout [h][pair], pre-scaled S3, b_b added
__device__ float g_a[(long)Hh*NN2];      // softmaxed attention [h][i][j]
__device__ float g_opt[Nn*288];
__device__ float g_part[(long)8*Nn*1536]; // opair partials [js][i][h*128+c]
__device__ float g_cat[Nn*DCAT];

typedef unsigned long long ull;
__device__ __forceinline__ void fma2(ull& d, ull a, ull b) {
    asm("fma.rn.f32x2 %0, %1, %2, %3;" : "=l"(d) : "l"(a), "l"(b), "l"(d));
}
__device__ __forceinline__ ull pack2(float x, float y) {
    ull d; asm("mov.b64 %0, {%1, %2};" : "=l"(d) : "f"(x), "f"(y)); return d;
}
__device__ __forceinline__ ull packdup(float x) {
    ull d; asm("mov.b64 %0, {%1, %1};" : "=l"(d) : "f"(x)); return d;
}
__device__ __forceinline__ float2 unpk(ull d) {
    float2 r; asm("mov.b64 {%0, %1}, %2;" : "=f"(r.x), "=f"(r.y) : "l"(d)); return r;
}

// ---------------- fused projections ----------------
__global__ void proj_gemm(const float* __restrict__ s,
    const float* __restrict__ w_q, const float* __restrict__ b_q,
    const float* __restrict__ w_kv, const float* __restrict__ b_kv,
    const float* __restrict__ w_qp, const float* __restrict__ b_qp,
    const float* __restrict__ w_kvp, const float* __restrict__ b_kvp) {
    __shared__ float As[16][68];
    __shared__ float Ws[16][33];
    int tid = threadIdx.x;
    int m0 = blockIdx.y * 64, n0 = blockIdx.x * 32;
    int col = tid & 31, rg = tid >> 5;
    int ar = tid >> 2, akg = tid & 3;
    ull acc0 = 0, acc1 = 0, acc2 = 0, acc3 = 0;
    const float* wrow = nullptr;
    int wc = tid >> 2, wkg = tid & 3;
    if (tid < 128) {
        int gc = n0 + wc;
        const float* W; int lc;
        if (gc < 192)      { W = w_q;   lc = gc; }
        else if (gc < 576) { W = w_kv;  lc = gc - 192; }
        else if (gc < 720) { W = w_qp;  lc = gc - 576; }
        else               { W = w_kvp; lc = gc - 720; }
        wrow = W + lc * CS;
    }
    for (int k0 = 0; k0 < CS; k0 += 16) {
        float4 av = *(const float4*)&s[(m0 + ar) * CS + k0 + 4 * akg];
        As[4*akg+0][ar] = av.x; As[4*akg+1][ar] = av.y;
        As[4*akg+2][ar] = av.z; As[4*akg+3][ar] = av.w;
        if (tid < 128) {
            float4 wv = *(const float4*)&wrow[k0 + 4 * wkg];
            Ws[4*wkg+0][wc] = wv.x; Ws[4*wkg+1][wc] = wv.y;
            Ws[4*wkg+2][wc] = wv.z; Ws[4*wkg+3][wc] = wv.w;
        }
        __syncthreads();
#pragma unroll
        for (int k2 = 0; k2 < 16; k2++) {
            ull w2 = packdup(Ws[k2][col]);
            ulonglong2 a0 = *(const ulonglong2*)&As[k2][rg * 8];
            ulonglong2 a1 = *(const ulonglong2*)&As[k2][rg * 8 + 4];
            fma2(acc0, a0.x, w2); fma2(acc1, a0.y, w2);
            fma2(acc2, a1.x, w2); fma2(acc3, a1.y, w2);
        }
        __syncthreads();
    }
    int gc = n0 + col;
    float bv;
    if (gc < 192)      bv = b_q[gc];
    else if (gc < 576) bv = b_kv[gc - 192];
    else if (gc < 720) bv = b_qp[gc - 576];
    else               bv = b_kvp[gc - 720];
    int mb = m0 + rg * 8;
    float2 r;
    r = unpk(acc0); g_proj[(mb+0)*NPROJ+gc] = r.x+bv; g_proj[(mb+1)*NPROJ+gc] = r.y+bv;
    r = unpk(acc1); g_proj[(mb+2)*NPROJ+gc] = r.x+bv; g_proj[(mb+3)*NPROJ+gc] = r.y+bv;
    r = unpk(acc2); g_proj[(mb+4)*NPROJ+gc] = r.x+bv; g_proj[(mb+5)*NPROJ+gc] = r.y+bv;
    r = unpk(acc3); g_proj[(mb+6)*NPROJ+gc] = r.x+bv; g_proj[(mb+7)*NPROJ+gc] = r.y+bv;
}

// ---------------- output GEMM ----------------
__global__ void gemm_out(const float* __restrict__ W, const float* __restrict__ bias,
                         float* __restrict__ C) {
    __shared__ float As[16][68];
    __shared__ float Ws[16][33];
    int tid = threadIdx.x;
    int m0 = blockIdx.y * 64, n0 = blockIdx.x * 32;
    int col = tid & 31, rg = tid >> 5;
    int ar = tid >> 2, akg = tid & 3;
    ull acc0 = 0, acc1 = 0, acc2 = 0, acc3 = 0;
    int wc = tid >> 2, wkg = tid & 3;
    const float* wrow = W + (n0 + wc) * DCAT;
    for (int k0 = 0; k0 < DCAT; k0 += 16) {
        float4 av = *(const float4*)&g_cat[(m0 + ar) * DCAT + k0 + 4 * akg];
        As[4*akg+0][ar] = av.x; As[4*akg+1][ar] = av.y;
        As[4*akg+2][ar] = av.z; As[4*akg+3][ar] = av.w;
        if (tid < 128) {
            float4 wv = *(const float4*)&wrow[k0 + 4 * wkg];
            Ws[4*wkg+0][wc] = wv.x; Ws[4*wkg+1][wc] = wv.y;
            Ws[4*wkg+2][wc] = wv.z; Ws[4*wkg+3][wc] = wv.w;
        }
        __syncthreads();
#pragma unroll
        for (int k2 = 0; k2 < 16; k2++) {
            ull w2 = packdup(Ws[k2][col]);
            ulonglong2 a0 = *(const ulonglong2*)&As[k2][rg * 8];
            ulonglong2 a1 = *(const ulonglong2*)&As[k2][rg * 8 + 4];
            fma2(acc0, a0.x, w2); fma2(acc1, a0.y, w2);
            fma2(acc2, a1.x, w2); fma2(acc3, a1.y, w2);
        }
        __syncthreads();
    }
    float bv = bias[n0 + col];
    int mb = m0 + rg * 8, gc = n0 + col;
    float2 r;
    r = unpk(acc0); C[(mb+0)*384+gc] = r.x+bv; C[(mb+1)*384+gc] = r.y+bv;
    r = unpk(acc1); C[(mb+2)*384+gc] = r.x+bv; C[(mb+3)*384+gc] = r.y+bv;
    r = unpk(acc2); C[(mb+4)*384+gc] = r.x+bv; C[(mb+5)*384+gc] = r.y+bv;
    r = unpk(acc3); C[(mb+6)*384+gc] = r.x+bv; C[(mb+7)*384+gc] = r.y+bv;
}

// ---------------- rotate+translate points ----------------
__global__ void point_kernel(const float* __restrict__ rot, const float* __restrict__ trans) {
    int i = blockIdx.x;
    int t = threadIdx.x;
    __shared__ float R[9], T[3];
    if (t < 9) R[t] = rot[i * 9 + t];
    if (t < 3) T[t] = trans[i * 3 + t];
    __syncthreads();
    if (t < 48) {
        const float* p = &g_proj[i * NPROJ + 576 + t * 3];
        float x = p[0], y = p[1], z = p[2];
        float* o = &g_qpts[i * 144 + t * 3];
        o[0] = R[0]*x + R[1]*y + R[2]*z + T[0];
        o[1] = R[3]*x + R[4]*y + R[5]*z + T[1];
        o[2] = R[6]*x + R[7]*y + R[8]*z + T[2];
    } else {
        int u = t - 48;
        const float* p = &g_proj[i * NPROJ + 720 + u * 3];
        float x = p[0], y = p[1], z = p[2];
        float* o = &g_kvpts[i * 432 + u * 3];
        o[0] = R[0]*x + R[1]*y + R[2]*z + T[0];
        o[1] = R[3]*x + R[4]*y + R[5]*z + T[1];
        o[2] = R[6]*x + R[7]*y + R[8]*z + T[2];
    }
}

// ---------------- transpose into [h][c][j] ----------------
__global__ void transpose_kernel() {
    int c = blockIdx.x, h = blockIdx.y;
    int tid = threadIdx.x;
    const float* src; int stride;
    if (c < 16)      { src = g_proj  + 192 + h * 32 + c;             stride = NPROJ; }
    else if (c < 28) { src = g_kvpts + h * 36 + (c - 16);            stride = 432; }
    else if (c < 44) { src = g_proj  + 192 + h * 32 + 16 + (c - 28); stride = NPROJ; }
    else             { src = g_kvpts + h * 36 + 12 + (c - 44);       stride = 432; }
    float* dst = g_T + (long)(h * 68 + c) * Nn;
    for (int j = tid; j < Nn; j += 256) dst[j] = src[(long)j * stride];
}

// ---------------- bias: warp per 64 pairs, w_b in registers, staged coalesced writes ----------------
__global__ __launch_bounds__(256) void bias_kernel(const float* __restrict__ z,
                                                   const float* __restrict__ w_b,
                                                   const float* __restrict__ b_b) {
    __shared__ float buf[8][12][66];     // per-warp staging [h][pair-in-chunk]
    int warp = threadIdx.x >> 5;
    int gwarp = (blockIdx.x * 256 + threadIdx.x) >> 5;  // 0..9215
    int lane = threadIdx.x & 31;
    // w registers: lane owns c = 4*lane .. 4*lane+3 for all 12 heads
    ull wA[12], wB[12];
#pragma unroll
    for (int h = 0; h < 12; h++) {
        float4 w4 = ((const float4*)(w_b + h * CZ))[lane];
        wA[h] = pack2(w4.x, w4.y); wB[h] = pack2(w4.z, w4.w);
    }
    // this lane's result role: heads base..base+2, valid on lanes with (lane&7)==0
    int base = ((lane >> 4) & 1) * 6 + ((lane >> 3) & 1) * 3;
    float bb0 = b_b[base], bb1 = b_b[base + 1], bb2 = b_b[base + 2];
    long p0 = (long)gwarp * 64;
    for (int t = 0; t < 64; t++) {
        long p = p0 + t;
        float4 zv = ((const float4*)(z + p * CZ))[lane];
        ull zA = pack2(zv.x, zv.y), zB = pack2(zv.z, zv.w);
        float v[12];
#pragma unroll
        for (int h = 0; h < 12; h++) {
            ull acc = 0;
            fma2(acc, zA, wA[h]); fma2(acc, zB, wB[h]);
            float2 f = unpk(acc);
            v[h] = f.x + f.y;
        }
        // round A (off=16): 12 -> 6
#pragma unroll
        for (int q = 0; q < 6; q++) {
            float t1 = __shfl_xor_sync(~0u, v[q], 16);
            float t2 = __shfl_xor_sync(~0u, v[6 + q], 16);
            v[q] = (lane & 16) ? (v[6 + q] + t2) : (v[q] + t1);
        }
        // round B (off=8): 6 -> 3
#pragma unroll
        for (int q = 0; q < 3; q++) {
            float t1 = __shfl_xor_sync(~0u, v[q], 8);
            float t2 = __shfl_xor_sync(~0u, v[3 + q], 8);
            v[q] = (lane & 8) ? (v[3 + q] + t2) : (v[q] + t1);
        }
        // rounds C-E: butterfly over remaining 8 lanes
#pragma unroll
        for (int off = 4; off; off >>= 1) {
#pragma unroll
            for (int q = 0; q < 3; q++) v[q] += __shfl_xor_sync(~0u, v[q], off);
        }
        if ((lane & 7) == 0) {
            buf[warp][base + 0][t] = S3 * (v[0] + bb0);
            buf[warp][base + 1][t] = S3 * (v[1] + bb1);
            buf[warp][base + 2][t] = S3 * (v[2] + bb2);
        }
        __syncwarp();
    }
    // coalesced flush: 12 rows of 64 into [h][pair] layout
#pragma unroll
    for (int r = 0; r < 12; r++) {
        g_bt[(long)r * NN2 + p0 + lane]      = buf[warp][r][lane];
        g_bt[(long)r * NN2 + p0 + 32 + lane] = buf[warp][r][lane + 32];
    }
}

// ---------------- logits + softmax: block per i, warp per head, logits in regs ----------------
__global__ __launch_bounds__(384) void attn2(const float* __restrict__ mask,
                                             const float* __restrict__ head_w) {
    __shared__ float qv[192], qpt[144], wcs[12];
    int i = blockIdx.x, tid = threadIdx.x;
    if (tid < 192) qv[tid] = g_proj[i * NPROJ + tid];
    else if (tid < 336) qpt[tid - 192] = g_qpts[i * 144 + (tid - 192)];
    else if (tid < 348) {
        int h = tid - 336;
        float hw = head_w[h];
        float sp = (hw > 20.f) ? hw : log1pf(expf(hw));
        wcs[h] = -0.5f * sp * 0.13608276348795434f;  // sqrt(1/54)
    }
    __syncthreads();
    int h = tid >> 5, lane = tid & 31;
    ull qhd[16], qpd[12];
#pragma unroll
    for (int c = 0; c < 16; c++) qhd[c] = packdup(qv[h * 16 + c]);
#pragma unroll
    for (int c = 0; c < 12; c++) qpd[c] = packdup(qpt[h * 12 + c]);
    float wc = wcs[h];
    float mi = mask[i];
    const float scale1 = 0.14433756729740643f;  // sqrt(1/48)
    const ull NEG1 = packdup(-1.f);
    const float* kT = g_T + (long)h * 68 * Nn;
    const float4* btp = (const float4*)(g_bt + (long)h * NN2 + (long)i * Nn);
    float lj[24];
#pragma unroll
    for (int k = 0; k < 6; k++) {
        int f4i = lane + 32 * k;          // float4 index; j0 = 4*f4i
        ull qkA = 0, qkB = 0;
#pragma unroll
        for (int c = 0; c < 16; c++) {
            float4 kv = ((const float4*)(kT + c * Nn))[f4i];
            fma2(qkA, qhd[c], pack2(kv.x, kv.y));
            fma2(qkB, qhd[c], pack2(kv.z, kv.w));
        }
        ull d2A = 0, d2B = 0;
#pragma unroll
        for (int c = 0; c < 12; c++) {
            float4 kv = ((const float4*)(kT + (16 + c) * Nn))[f4i];
            ull tA = qpd[c], tB = qpd[c];
            fma2(tA, pack2(kv.x, kv.y), NEG1);
            fma2(tB, pack2(kv.z, kv.w), NEG1);
            fma2(d2A, tA, tA);
            fma2(d2B, tB, tB);
        }
        float4 m4 = ((const float4*)mask)[f4i];
        float4 b4 = btp[f4i];
        float2 qA = unpk(qkA), qB = unpk(qkB);
        float2 dA = unpk(d2A), dB = unpk(d2B);
        lj[4*k+0] = qA.x * scale1 + b4.x + wc * dA.x + INFV * (mi * m4.x - 1.f);
        lj[4*k+1] = qA.y * scale1 + b4.y + wc * dA.y + INFV * (mi * m4.y - 1.f);
        lj[4*k+2] = qB.x * scale1 + b4.z + wc * dB.x + INFV * (mi * m4.z - 1.f);
        lj[4*k+3] = qB.y * scale1 + b4.w + wc * dB.y + INFV * (mi * m4.w - 1.f);
    }
    // softmax over 768 (24 regs x 32 lanes)
    float m = -1e30f;
#pragma unroll
    for (int k = 0; k < 24; k++) m = fmaxf(m, lj[k]);
#pragma unroll
    for (int o = 16; o; o >>= 1) m = fmaxf(m, __shfl_xor_sync(~0u, m, o));
    float ssum = 0.f;
#pragma unroll
    for (int k = 0; k < 24; k++) { lj[k] = __expf(lj[k] - m); ssum += lj[k]; }
#pragma unroll
    for (int o = 16; o; o >>= 1) ssum += __shfl_xor_sync(~0u, ssum, o);
    float inv = 1.f / ssum;
    float4* arow = (float4*)(g_a + (long)h * NN2 + (long)i * Nn);
#pragma unroll
    for (int k = 0; k < 6; k++) {
        float4 o4 = make_float4(lj[4*k]*inv, lj[4*k+1]*inv, lj[4*k+2]*inv, lj[4*k+3]*inv);
        arow[lane + 32 * k] = o4;
    }
}

// ---------------- o and o_pt: per (h, i-tile 64) ----------------
__global__ void ov_kernel() {
    __shared__ float As[64][68];
    __shared__ float Vs[64][40];
    int h = blockIdx.y;
    int i0 = blockIdx.x * 64;
    int tid = threadIdx.x;
    int ii = tid >> 2, cs = tid & 3;
    float acc[10];
#pragma unroll
    for (int r = 0; r < 10; r++) acc[r] = 0.f;
    const float* vT = &g_T[(long)(h * 68 + 28) * Nn];
    for (int j0 = 0; j0 < Nn; j0 += 64) {
#pragma unroll
        for (int v = 0; v < 4; v++) {
            int idx = tid + v * 256;
            int row = idx >> 4, c4 = idx & 15;
            float4 val = *(const float4*)&g_a[(long)h * NN2 + (long)(i0 + row) * Nn + j0 + 4 * c4];
            *(float4*)&As[row][4 * c4] = val;
        }
        for (int u = tid; u < 64 * 40; u += 256) {
            int c = u >> 6, jj = u & 63;
            Vs[jj][c] = vT[(long)c * Nn + j0 + jj];
        }
        __syncthreads();
#pragma unroll
        for (int jj = 0; jj < 64; jj++) {
            float av = As[ii][jj];
#pragma unroll
            for (int r = 0; r < 10; r++) acc[r] += av * Vs[jj][cs + 4 * r];
        }
        __syncthreads();
    }
    int i = i0 + ii;
#pragma unroll
    for (int r = 0; r < 10; r++) {
        int c = cs + 4 * r;
        if (c < 16) g_cat[i * DCAT + h * 16 + c] = acc[r];
        else        g_opt[i * 288 + h * 24 + (c - 16)] = acc[r];
    }
}

// ---------------- o_pt -> local frame + norm ----------------
__global__ void epi_kernel(const float* __restrict__ rot, const float* __restrict__ trans) {
    int i = blockIdx.x;
    int t = threadIdx.x;
    __shared__ float R[9], T[3];
    if (t < 9) R[t] = rot[i * 9 + t];
    if (t < 3) T[t] = trans[i * 3 + t];
    __syncthreads();
    const float* op = &g_opt[i * 288 + t * 3];
    float x = op[0] - T[0], y = op[1] - T[1], z = op[2] - T[2];
    float lx = R[0]*x + R[3]*y + R[6]*z;
    float ly = R[1]*x + R[4]*y + R[7]*z;
    float lz = R[2]*x + R[5]*y + R[8]*z;
    float nrm = sqrtf(lx*lx + ly*ly + lz*lz + 1e-8f);
    float* c1 = &g_cat[i * DCAT + 192 + t * 3];
    c1[0] = lx; c1[1] = ly; c1[2] = lz;
    g_cat[i * DCAT + 480 + t] = nrm;
}

// ---------------- o_pair: warp per (i, j-split); partials to g_part ----------------
__global__ __launch_bounds__(256) void opair3(const float* __restrict__ z) {
    int i = blockIdx.x;
    int js = threadIdx.x >> 5, lane = threadIdx.x & 31;
    ull accA[12], accB[12];
#pragma unroll
    for (int h = 0; h < 12; h++) { accA[h] = 0; accB[h] = 0; }
    const float4* zp = (const float4*)(z + (long)i * Nn * CZ);
    const float* ap = g_a + (long)i * Nn;
    int jbeg = js * 96;
#pragma unroll 4
    for (int j = jbeg; j < jbeg + 96; j++) {
        float4 zv = zp[j * 32 + lane];
        ull zA = pack2(zv.x, zv.y), zB = pack2(zv.z, zv.w);
#pragma unroll
        for (int h = 0; h < 12; h++) {
            ull av = packdup(ap[(long)h * NN2 + j]);
            fma2(accA[h], av, zA);
            fma2(accB[h], av, zB);
        }
    }
    float4* dst = (float4*)(g_part + ((long)js * Nn + i) * 1536);
#pragma unroll
    for (int h = 0; h < 12; h++) {
        float2 a = unpk(accA[h]), b = unpk(accB[h]);
        dst[h * 32 + lane] = make_float4(a.x, a.y, b.x, b.y);
    }
}

__global__ void opair_reduce() {
    int i = blockIdx.x, t = threadIdx.x;  // 384 threads, 4 floats each
    float4 s = make_float4(0.f, 0.f, 0.f, 0.f);
#pragma unroll
    for (int js = 0; js < 8; js++) {
        float4 p = ((const float4*)(g_part + ((long)js * Nn + i) * 1536))[t];
        s.x += p.x; s.y += p.y; s.z += p.z; s.w += p.w;
    }
    ((float4*)(g_cat + i * DCAT + 576))[t] = s;
}

extern "C" void kernel_launch(void* const* d_in, const int* in_sizes, int n_in,
                              void* d_out, int out_size) {
    const float* s       = (const float*)d_in[0];
    const float* z       = (const float*)d_in[1];
    const float* rot     = (const float*)d_in[2];
    const float* trans   = (const float*)d_in[3];
    const float* mask    = (const float*)d_in[4];
    const float* w_q     = (const float*)d_in[5];
    const float* b_q     = (const float*)d_in[6];
    const float* w_kv    = (const float*)d_in[7];
    const float* b_kv    = (const float*)d_in[8];
    const float* w_qp    = (const float*)d_in[9];
    const float* b_qp    = (const float*)d_in[10];
    const float* w_kvp   = (const float*)d_in[11];
    const float* b_kvp   = (const float*)d_in[12];
    const float* w_b     = (const float*)d_in[13];
    const float* b_b     = (const float*)d_in[14];
    const float* head_w  = (const float*)d_in[15];
    const float* w_out   = (const float*)d_in[16];
    const float* b_out   = (const float*)d_in[17];
    float* out = (float*)d_out;

    bias_kernel<<<1152, 256>>>(z, w_b, b_b);
    proj_gemm<<<dim3(36, 12), 256>>>(s, w_q, b_q, w_kv, b_kv, w_qp, b_qp, w_kvp, b_kvp);
    point_kernel<<<Nn, 192>>>(rot, trans);
    transpose_kernel<<<dim3(68, 12), 256>>>();
    attn2<<<Nn, 384>>>(mask, head_w);
    ov_kernel<<<dim3(Nn / 64, Hh), 256>>>();
    epi_kernel<<<Nn, 96>>>(rot, trans);
    opair3<<<Nn, 256>>>(z);
    opair_reduce<<<Nn, 384>>>();
    gemm_out<<<dim3(12, 12), 256>>>(w_out, b_out, out);
}